// round 3
// baseline (speedup 1.0000x reference)
#include <cuda_runtime.h>

// Problem constants
#define NL    6        // layers
#define DIMV  40       // state dim
#define ADIMV 20       // half dim
#define HHV   128      // hidden
#define DINV  276      // ADIM + 2*H
#define BATCH 131072
#define CLIPV 2.0f

// Tiling
#define TB 128         // rows per block
#define NT 256         // threads per block
#define HP 132         // h buffer pitch (floats), padded
#define ZP 44          // z tile pitch (floats)

// SMEM layout (floats):
//  hA [TB*HP], hB [TB*HP], zt [TB*ZP], wst [H*ADIM], wtt [H*ADIM], ldet [TB],
//  then 4 int arrays [NL*ADIM] each.
#define SMEM_FLOATS (2*TB*HP + TB*ZP + 2*HHV*ADIMV + TB)
#define SMEM_BYTES  (SMEM_FLOATS*4 + 4*NL*ADIMV*4)

__device__ __forceinline__ float silu_f(float v) {
    return v / (1.0f + __expf(-v));
}

__device__ __forceinline__ void fma8x8(float (&acc)[8][8], const float (&a)[8],
                                       float4 w0, float4 w1) {
    float w[8];
    w[0] = w0.x; w[1] = w0.y; w[2] = w0.z; w[3] = w0.w;
    w[4] = w1.x; w[5] = w1.y; w[6] = w1.z; w[7] = w1.w;
#pragma unroll
    for (int i = 0; i < 8; ++i)
#pragma unroll
        for (int j = 0; j < 8; ++j)
            acc[i][j] = fmaf(a[i], w[j], acc[i][j]);
}

// C[128x128] += A_smem[128xK=128, pitch HP] @ W[K=128 x 128 row-major]
__device__ __forceinline__ void gemm_smem128(const float* __restrict__ A,
                                             const float* __restrict__ W,
                                             float (&acc)[8][8], int r0, int c0) {
    for (int k0 = 0; k0 < HHV; k0 += 4) {
        float4 a4[8];
#pragma unroll
        for (int i = 0; i < 8; ++i)
            a4[i] = *(const float4*)&A[(r0 + i) * HP + k0];
#pragma unroll
        for (int kk = 0; kk < 4; ++kk) {
            float a[8];
#pragma unroll
            for (int i = 0; i < 8; ++i)
                a[i] = ((const float*)&a4[i])[kk];
            const float* wr = W + (k0 + kk) * HHV + c0;
            fma8x8(acc, a, *(const float4*)wr, *(const float4*)(wr + 4));
        }
    }
}

// bias + silu -> dst smem (pitch HP)
__device__ __forceinline__ void epilogue_silu(const float (&acc)[8][8],
                                              const float* __restrict__ bias,
                                              float* __restrict__ dst,
                                              int r0, int c0) {
    float bb[8];
    {
        float4 b0 = *(const float4*)(bias + c0);
        float4 b1 = *(const float4*)(bias + c0 + 4);
        bb[0] = b0.x; bb[1] = b0.y; bb[2] = b0.z; bb[3] = b0.w;
        bb[4] = b1.x; bb[5] = b1.y; bb[6] = b1.z; bb[7] = b1.w;
    }
#pragma unroll
    for (int i = 0; i < 8; ++i) {
        float4 o0, o1;
        o0.x = silu_f(acc[i][0] + bb[0]);
        o0.y = silu_f(acc[i][1] + bb[1]);
        o0.z = silu_f(acc[i][2] + bb[2]);
        o0.w = silu_f(acc[i][3] + bb[3]);
        o1.x = silu_f(acc[i][4] + bb[4]);
        o1.y = silu_f(acc[i][5] + bb[5]);
        o1.z = silu_f(acc[i][6] + bb[6]);
        o1.w = silu_f(acc[i][7] + bb[7]);
        *(float4*)&dst[(r0 + i) * HP + c0]     = o0;
        *(float4*)&dst[(r0 + i) * HP + c0 + 4] = o1;
    }
}

__global__ __launch_bounds__(NT, 1)
void biflow_kernel(const float* __restrict__ x,
                   const float* __restrict__ ctx,
                   const float* __restrict__ te,
                   const float* __restrict__ W1, const float* __restrict__ b1,
                   const float* __restrict__ W2, const float* __restrict__ b2,
                   const float* __restrict__ W3, const float* __restrict__ b3,
                   const float* __restrict__ Ws, const float* __restrict__ bs,
                   const float* __restrict__ Wt, const float* __restrict__ bt,
                   const int*   __restrict__ perm,
                   const int*   __restrict__ idx_a,
                   const int*   __restrict__ idx_b,
                   float* __restrict__ out)
{
    extern __shared__ float sm[];
    float* hA   = sm;                    // TB*HP
    float* hB   = hA + TB * HP;          // TB*HP
    float* zt   = hB + TB * HP;          // TB*ZP
    float* wst  = zt + TB * ZP;          // H*ADIM
    float* wtt  = wst + HHV * ADIMV;     // H*ADIM
    float* ldet = wtt + HHV * ADIMV;     // TB
    int* sa_s = (int*)(ldet + TB);       // NL*ADIM
    int* sb_s = sa_s + NL * ADIMV;
    int* da_s = sb_s + NL * ADIMV;
    int* db_s = da_s + NL * ADIMV;

    const int tid  = threadIdx.x;
    const int row0 = blockIdx.x * TB;

    // ---- init: load z tile, zero logdet, compose indices ----
    for (int idx = tid; idx < TB * DIMV; idx += NT) {
        int r = idx / DIMV, c = idx % DIMV;
        zt[r * ZP + c] = x[(row0 + r) * DIMV + c];
    }
    if (tid < TB) ldet[tid] = 0.0f;
    if (tid < NL * ADIMV) {
        int l  = tid / ADIMV;
        int ia = idx_a[tid];
        int ib = idx_b[tid];
        da_s[tid] = ia;
        db_s[tid] = ib;
        sa_s[tid] = perm[l * DIMV + ia];   // source of z_a[k]
        sb_s[tid] = perm[l * DIMV + ib];   // source of z_b[k]
    }
    __syncthreads();

    const int ty = tid >> 4, tx = tid & 15;
    const int r0 = ty * 8, c0 = tx * 8;
    const int rr = tid >> 1, q = tid & 1, j0 = q * 10;

    const float* ctxb = ctx + (long long)row0 * HHV;
    const float* teb  = te  + (long long)row0 * HHV;

    for (int l = 0; l < NL; ++l) {
        // ======== GEMM1: h1 = silu([z_a, ctx, te] @ W1 + b1) ========
        float acc[8][8];
#pragma unroll
        for (int i = 0; i < 8; ++i)
#pragma unroll
            for (int j = 0; j < 8; ++j) acc[i][j] = 0.0f;

        const float* w1 = W1 + l * DINV * HHV;

        // segment 1: z_a gather (K = 20)
        for (int k = 0; k < ADIMV; ++k) {
            int col = sa_s[l * ADIMV + k];
            float a[8];
#pragma unroll
            for (int i = 0; i < 8; ++i) a[i] = zt[(r0 + i) * ZP + col];
            const float* wr = w1 + k * HHV + c0;
            fma8x8(acc, a, *(const float4*)wr, *(const float4*)(wr + 4));
        }
        // segment 2: ctx (K = 128, W1 rows 20..147)
        for (int k0 = 0; k0 < HHV; k0 += 4) {
            float4 a4[8];
#pragma unroll
            for (int i = 0; i < 8; ++i)
                a4[i] = *(const float4*)&ctxb[(r0 + i) * HHV + k0];
#pragma unroll
            for (int kk = 0; kk < 4; ++kk) {
                float a[8];
#pragma unroll
                for (int i = 0; i < 8; ++i) a[i] = ((const float*)&a4[i])[kk];
                const float* wr = w1 + (ADIMV + k0 + kk) * HHV + c0;
                fma8x8(acc, a, *(const float4*)wr, *(const float4*)(wr + 4));
            }
        }
        // segment 3: te (K = 128, W1 rows 148..275)
        for (int k0 = 0; k0 < HHV; k0 += 4) {
            float4 a4[8];
#pragma unroll
            for (int i = 0; i < 8; ++i)
                a4[i] = *(const float4*)&teb[(r0 + i) * HHV + k0];
#pragma unroll
            for (int kk = 0; kk < 4; ++kk) {
                float a[8];
#pragma unroll
                for (int i = 0; i < 8; ++i) a[i] = ((const float*)&a4[i])[kk];
                const float* wr = w1 + (ADIMV + HHV + k0 + kk) * HHV + c0;
                fma8x8(acc, a, *(const float4*)wr, *(const float4*)(wr + 4));
            }
        }
        epilogue_silu(acc, b1 + l * HHV, hA, r0, c0);
        __syncthreads();

        // ======== GEMM2: h2 = silu(h1 @ W2 + b2) ========
#pragma unroll
        for (int i = 0; i < 8; ++i)
#pragma unroll
            for (int j = 0; j < 8; ++j) acc[i][j] = 0.0f;
        gemm_smem128(hA, W2 + l * HHV * HHV, acc, r0, c0);
        epilogue_silu(acc, b2 + l * HHV, hB, r0, c0);
        __syncthreads();

        // ======== GEMM3: h3 = silu(h2 @ W3 + b3) ========
#pragma unroll
        for (int i = 0; i < 8; ++i)
#pragma unroll
            for (int j = 0; j < 8; ++j) acc[i][j] = 0.0f;
        gemm_smem128(hB, W3 + l * HHV * HHV, acc, r0, c0);
        epilogue_silu(acc, b3 + l * HHV, hA, r0, c0);
        __syncthreads();

        // ======== stage Ws/Wt for this layer into smem ========
        {
            const float4* wsl = (const float4*)(Ws + l * HHV * ADIMV);
            const float4* wtl = (const float4*)(Wt + l * HHV * ADIMV);
            for (int idx = tid; idx < HHV * ADIMV / 4; idx += NT) {
                ((float4*)wst)[idx] = wsl[idx];
                ((float4*)wtt)[idx] = wtl[idx];
            }
        }
        __syncthreads();

        // ======== s/t heads + coupling ========
        // thread: row rr (0..127), q in {0,1} handles cols j0..j0+9 of both s and t
        float accS[10], accT[10];
#pragma unroll
        for (int p = 0; p < 10; ++p) { accS[p] = 0.0f; accT[p] = 0.0f; }

        for (int k = 0; k < HHV; ++k) {
            float hv = hA[rr * HP + k];
            const float2* ws2 = (const float2*)&wst[k * ADIMV + j0];
            const float2* wt2 = (const float2*)&wtt[k * ADIMV + j0];
#pragma unroll
            for (int p = 0; p < 5; ++p) {
                float2 aw = ws2[p];
                float2 bw = wt2[p];
                accS[2 * p]     = fmaf(hv, aw.x, accS[2 * p]);
                accS[2 * p + 1] = fmaf(hv, aw.y, accS[2 * p + 1]);
                accT[2 * p]     = fmaf(hv, bw.x, accT[2 * p]);
                accT[2 * p + 1] = fmaf(hv, bw.y, accT[2 * p + 1]);
            }
        }

        float lsum = 0.0f;
        float za[10], yb[10];
#pragma unroll
        for (int p = 0; p < 10; ++p) {
            int j = j0 + p;
            float s = accS[p] + bs[l * ADIMV + j];
            s = fminf(fmaxf(s, -CLIPV), CLIPV);
            float t  = accT[p] + bt[l * ADIMV + j];
            float zb = zt[rr * ZP + sb_s[l * ADIMV + j]];
            yb[p] = fmaf(zb, __expf(s), t);
            za[p] = zt[rr * ZP + sa_s[l * ADIMV + j]];
            lsum += s;
        }
        __syncthreads();   // all gathers from zt done before any scatter
#pragma unroll
        for (int p = 0; p < 10; ++p) {
            int j = j0 + p;
            zt[rr * ZP + da_s[l * ADIMV + j]] = za[p];
            zt[rr * ZP + db_s[l * ADIMV + j]] = yb[p];
        }
        float other = __shfl_down_sync(0xffffffffu, lsum, 1);
        if (q == 0) ldet[rr] += lsum + other;
        __syncthreads();   // zt / ldet settled for next layer
    }

    // ---- write output: z (B x 40) then logdet (B) ----
    for (int idx = tid; idx < TB * DIMV; idx += NT) {
        int r = idx / DIMV, c = idx % DIMV;
        out[(long long)(row0 + r) * DIMV + c] = zt[r * ZP + c];
    }
    if (tid < TB)
        out[(long long)BATCH * DIMV + row0 + tid] = ldet[tid];
}

extern "C" void kernel_launch(void* const* d_in, const int* in_sizes, int n_in,
                              void* d_out, int out_size) {
    const float* x    = (const float*)d_in[0];
    const float* ctx  = (const float*)d_in[1];
    const float* te   = (const float*)d_in[2];
    const float* W1   = (const float*)d_in[3];
    const float* b1   = (const float*)d_in[4];
    const float* W2   = (const float*)d_in[5];
    const float* b2   = (const float*)d_in[6];
    const float* W3   = (const float*)d_in[7];
    const float* b3   = (const float*)d_in[8];
    const float* Ws   = (const float*)d_in[9];
    const float* bs   = (const float*)d_in[10];
    const float* Wt   = (const float*)d_in[11];
    const float* bt   = (const float*)d_in[12];
    const int*   perm = (const int*)d_in[13];
    const int*   ia   = (const int*)d_in[14];
    const int*   ib   = (const int*)d_in[15];
    float* out = (float*)d_out;

    cudaFuncSetAttribute(biflow_kernel,
                         cudaFuncAttributeMaxDynamicSharedMemorySize, SMEM_BYTES);

    biflow_kernel<<<BATCH / TB, NT, SMEM_BYTES>>>(
        x, ctx, te, W1, b1, W2, b2, W3, b3, Ws, bs, Wt, bt, perm, ia, ib, out);
}